// round 6
// baseline (speedup 1.0000x reference)
#include <cuda_runtime.h>
#include <cstdint>

#define B_  8
#define C_  128
#define H_  192
#define W_  448
#define ND  49

#define TX  32
#define TY  16
#define KC  8
#define NCHUNK (C_ / KC)
#define NT  256

#define S1_ROW 32
#define S2_ROW 44                   // logical x in [-4, TX+7] -> idx = x+4
#define S1_CH  (TY * S1_ROW)        // 512
#define S2_CH  ((TY + 6) * S2_ROW)  // 968
#define S1_SIZE (KC * S1_CH)        // 4096
#define S2_SIZE (KC * S2_CH)        // 7744
#define BUF_SIZE (S1_SIZE + S2_SIZE)               // 11840 floats
#define SMEM_BYTES (2 * BUF_SIZE * sizeof(float))  // 94720 B

__device__ __forceinline__ uint32_t sptr(const void* p) {
    return (uint32_t)__cvta_generic_to_shared(p);
}
__device__ __forceinline__ void cp16(void* dst, const float* src, bool pred) {
    int bytes = pred ? 16 : 0;
    asm volatile("cp.async.cg.shared.global [%0], [%1], 16, %2;\n"
                 :: "r"(sptr(dst)), "l"(src), "r"(bytes));
}
__device__ __forceinline__ void cp4(void* dst, const float* src, bool pred) {
    int bytes = pred ? 4 : 0;
    asm volatile("cp.async.ca.shared.global [%0], [%1], 4, %2;\n"
                 :: "r"(sptr(dst)), "l"(src), "r"(bytes));
}
__device__ __forceinline__ void cp_commit() {
    asm volatile("cp.async.commit_group;\n" ::: "memory");
}
// 32-bit shared-window vector load: 1-register address, minimal ALU.
__device__ __forceinline__ float4 lds128(uint32_t addr) {
    float4 r;
    asm volatile("ld.shared.v4.f32 {%0,%1,%2,%3}, [%4];"
                 : "=f"(r.x), "=f"(r.y), "=f"(r.z), "=f"(r.w) : "r"(addr));
    return r;
}

__device__ __forceinline__ void load_chunk(
    float* __restrict__ s1, float* __restrict__ s2,
    const float* __restrict__ fbase, const float* __restrict__ sbase,
    int c0, int x0, int y0, int tid)
{
    const size_t HW = (size_t)H_ * W_;
    // ---- first tile: 8ch x 16 rows x 8 float4 = 1024 units ----
#pragma unroll
    for (int it = 0; it < 4; ++it) {
        int u = tid + it * NT;
        int c = u >> 7;
        int rem = u & 127;
        int row = rem >> 3;
        int q = rem & 7;
        const float* src = fbase + (size_t)(c0 + c) * HW + (size_t)(y0 + row) * W_ + x0 + q * 4;
        cp16(s1 + c * S1_CH + row * S1_ROW + q * 4, src, true);
    }
    // ---- second interior: 8ch x 22 rows x 8 float4 = 1408 units ----
#pragma unroll
    for (int it = 0; it < 6; ++it) {
        int u = tid + it * NT;
        if (it < 5 || u < 1408) {
            int c = u / 176;
            int rem = u - c * 176;
            int row = rem >> 3;
            int q = rem & 7;
            int gy = y0 - 3 + row;
            bool p = (gy >= 0) && (gy < H_);
            int gyc = gy < 0 ? 0 : (gy >= H_ ? H_ - 1 : gy);
            const float* src = sbase + (size_t)(c0 + c) * HW + (size_t)gyc * W_ + x0 + q * 4;
            cp16(s2 + c * S2_CH + row * S2_ROW + 4 + q * 4, src, p);
        }
    }
    // ---- second edges: 8ch x 22 rows x 6 scalars = 1056 units ----
#pragma unroll
    for (int it = 0; it < 5; ++it) {
        int u = tid + it * NT;
        if (it < 4 || u < 1056) {
            int c = u / 132;
            int rem = u - c * 132;
            int row = rem / 6;
            int e = rem - row * 6;
            int x = (e < 3) ? (e - 3) : (TX + e - 3);
            int gy = y0 - 3 + row;
            int gx = x0 + x;
            bool p = (gy >= 0) && (gy < H_) && (gx >= 0) && (gx < W_);
            int gyc = gy < 0 ? 0 : (gy >= H_ ? H_ - 1 : gy);
            int gxc = gx < 0 ? 0 : (gx >= W_ ? W_ - 1 : gx);
            const float* src = sbase + (size_t)(c0 + c) * HW + (size_t)gyc * W_ + gxc;
            cp4(s2 + c * S2_CH + row * S2_ROW + (x + 4), src, p);
        }
    }
}

// One smem row, displacements di in [DI0, DI1), 4 px/thread.
// vaddr = byte address of this row at float index txl*4.
// acc packed as (di-DI0)*4 + p.
template<int DI0, int DI1>
__device__ __forceinline__ void row_acc(
    uint32_t vaddr, float4 f, float* __restrict__ acc)
{
    constexpr int B0 = (DI0 + 1) / 4;
    constexpr int B1 = (DI1 + 3) / 4;   // max j = (DI1-1)+3+1
    float v[12];
#pragma unroll
    for (int bq = B0; bq <= B1; ++bq) {
        float4 t = lds128(vaddr + bq * 16);
        v[bq * 4 + 0] = t.x; v[bq * 4 + 1] = t.y;
        v[bq * 4 + 2] = t.z; v[bq * 4 + 3] = t.w;
    }
#pragma unroll
    for (int di = DI0; di < DI1; ++di) {
        acc[(di - DI0) * 4 + 0] += f.x * v[di + 1];
        acc[(di - DI0) * 4 + 1] += f.y * v[di + 2];
        acc[(di - DI0) * 4 + 2] += f.z * v[di + 3];
        acc[(di - DI0) * 4 + 3] += f.w * v[di + 4];
    }
}

// G0: d[0,24)  = rr0[0,7) rr1[0,7) rr2[0,7) rr3[0,3)  -> 96 acc
// G1: d[24,49) = rr3[3,7) rr4[0,7) rr5[0,7) rr6[0,7)  -> 100 acc
template<int G>
__device__ __forceinline__ void accumulate(
    uint32_t s1a, uint32_t s2a, float* __restrict__ acc)
{
#pragma unroll 1
    for (int c = 0; c < KC; ++c) {
        float4 f = lds128(s1a);
        s1a += S1_CH * 4;
        if (G == 0) {
            row_acc<0, 7>(s2a + 0 * (S2_ROW * 4), f, acc + 0);
            row_acc<0, 7>(s2a + 1 * (S2_ROW * 4), f, acc + 28);
            row_acc<0, 7>(s2a + 2 * (S2_ROW * 4), f, acc + 56);
            row_acc<0, 3>(s2a + 3 * (S2_ROW * 4), f, acc + 84);
        } else {
            row_acc<3, 7>(s2a + 3 * (S2_ROW * 4), f, acc + 0);
            row_acc<0, 7>(s2a + 4 * (S2_ROW * 4), f, acc + 16);
            row_acc<0, 7>(s2a + 5 * (S2_ROW * 4), f, acc + 44);
            row_acc<0, 7>(s2a + 6 * (S2_ROW * 4), f, acc + 72);
        }
        s2a += S2_CH * 4;
    }
}

template<int NSEG>
__device__ __forceinline__ void store_seg(
    float* __restrict__ op, const float* __restrict__ acc)
{
    const float invC = 1.0f / (float)C_;
#pragma unroll
    for (int i = 0; i < NSEG; ++i) {
        float4 o;
        o.x = acc[i * 4 + 0] * invC;
        o.y = acc[i * 4 + 1] * invC;
        o.z = acc[i * 4 + 2] * invC;
        o.w = acc[i * 4 + 3] * invC;
        *(float4*)op = o;
        op += (size_t)H_ * W_;
    }
}

__global__ void __launch_bounds__(NT, 2)
corr_kernel(const float* __restrict__ first,
            const float* __restrict__ second,
            float* __restrict__ out)
{
    extern __shared__ float smem[];
    const int tid = threadIdx.x;
    const int wg   = tid >> 7;        // warpgroup 0 or 1 (displacement split)
    const int wtid = tid & 127;
    const int bx = blockIdx.x, by = blockIdx.y, b = blockIdx.z;
    const int x0 = bx * TX, y0 = by * TY;
    const int txl = wtid & 7;         // 0..7, owns 4 x-pixels
    const int tyl = wtid >> 3;        // 0..15, one y-row

    const size_t HW = (size_t)H_ * W_;
    const float* fbase = first  + (size_t)b * C_ * HW;
    const float* sbase = second + (size_t)b * C_ * HW;

    const uint32_t smem_base = sptr(smem);
    const uint32_t s1_thr = smem_base + (tyl * S1_ROW + txl * 4) * 4;
    const uint32_t s2_thr = smem_base + S1_SIZE * 4 + (tyl * S2_ROW + txl * 4) * 4;

    float acc[100];
#pragma unroll
    for (int i = 0; i < 100; ++i) acc[i] = 0.0f;

    load_chunk(smem, smem + S1_SIZE, fbase, sbase, 0, x0, y0, tid);
    cp_commit();

#pragma unroll 1
    for (int k = 0; k < NCHUNK; ++k) {
        if (k < NCHUNK - 1) {
            float* nb = smem + ((k + 1) & 1) * BUF_SIZE;
            load_chunk(nb, nb + S1_SIZE, fbase, sbase, (k + 1) * KC, x0, y0, tid);
            cp_commit();
            asm volatile("cp.async.wait_group 1;\n" ::: "memory");
        } else {
            asm volatile("cp.async.wait_group 0;\n" ::: "memory");
        }
        __syncthreads();

        const uint32_t boff = (uint32_t)((k & 1) * BUF_SIZE * 4);
        if (wg == 0) accumulate<0>(s1_thr + boff, s2_thr + boff, acc);
        else         accumulate<1>(s1_thr + boff, s2_thr + boff, acc);

        __syncthreads();
    }

    const int y = y0 + tyl;
    const int x = x0 + txl * 4;
    if (wg == 0) {
        float* op = out + (((size_t)b * ND + 0) * H_ + y) * W_ + x;
        store_seg<24>(op, acc);
    } else {
        float* op = out + (((size_t)b * ND + 24) * H_ + y) * W_ + x;
        store_seg<25>(op, acc);
    }
}

extern "C" void kernel_launch(void* const* d_in, const int* in_sizes, int n_in,
                              void* d_out, int out_size)
{
    const float* first  = (const float*)d_in[0];
    const float* second = (const float*)d_in[1];
    float* out = (float*)d_out;

    cudaFuncSetAttribute(corr_kernel,
                         cudaFuncAttributeMaxDynamicSharedMemorySize,
                         (int)SMEM_BYTES);

    dim3 grid(W_ / TX, H_ / TY, B_);   // 14 x 12 x 8 = 1344 CTAs
    dim3 block(NT);
    corr_kernel<<<grid, block, SMEM_BYTES>>>(first, second, out);
}

// round 7
// speedup vs baseline: 1.2939x; 1.2939x over previous
#include <cuda_runtime.h>
#include <cstdint>

#define B_  8
#define C_  128
#define H_  192
#define W_  448
#define ND  49

#define TX  32
#define TY  24
#define KC  8
#define NCHUNK (C_ / KC)
#define NT  384          // 4 groups x 96 threads

#define S1_ROW 36                   // padded (bank spread for f loads)
#define S1_CH  (TY * S1_ROW)        // 864
#define S2_ROW 44                   // logical x in [-4, 39] -> idx = x+4
#define S2_CH  ((TY + 6) * S2_ROW)  // 30*44 = 1320
#define S1_SIZE (KC * S1_CH)        // 6912
#define S2_SIZE (KC * S2_CH)        // 10560
#define BUF_SIZE (S1_SIZE + S2_SIZE)               // 17472 floats
#define SMEM_BYTES (2 * BUF_SIZE * sizeof(float))  // 139776 B

__device__ __forceinline__ uint32_t sptr(const void* p) {
    return (uint32_t)__cvta_generic_to_shared(p);
}
__device__ __forceinline__ void cp16(void* dst, const float* src, bool pred) {
    int bytes = pred ? 16 : 0;
    asm volatile("cp.async.cg.shared.global [%0], [%1], 16, %2;\n"
                 :: "r"(sptr(dst)), "l"(src), "r"(bytes));
}
__device__ __forceinline__ void cp4(void* dst, const float* src, bool pred) {
    int bytes = pred ? 4 : 0;
    asm volatile("cp.async.ca.shared.global [%0], [%1], 4, %2;\n"
                 :: "r"(sptr(dst)), "l"(src), "r"(bytes));
}
__device__ __forceinline__ void cp_commit() {
    asm volatile("cp.async.commit_group;\n" ::: "memory");
}
__device__ __forceinline__ float4 lds128(uint32_t addr) {
    float4 r;
    asm volatile("ld.shared.v4.f32 {%0,%1,%2,%3}, [%4];"
                 : "=f"(r.x), "=f"(r.y), "=f"(r.z), "=f"(r.w) : "r"(addr));
    return r;
}

__device__ __forceinline__ void load_chunk(
    float* __restrict__ s1, float* __restrict__ s2,
    const float* __restrict__ fbase, const float* __restrict__ sbase,
    int c0, int x0, int y0, int tid)
{
    const size_t HW = (size_t)H_ * W_;
    // ---- first tile: 8ch x 24 rows x 8 float4 = 1536 units (4 iters @384) ----
#pragma unroll
    for (int it = 0; it < 4; ++it) {
        int u = tid + it * NT;
        int c = u / 192;
        int rem = u - c * 192;
        int row = rem >> 3;
        int q = rem & 7;
        const float* src = fbase + (size_t)(c0 + c) * HW + (size_t)(y0 + row) * W_ + x0 + q * 4;
        cp16(s1 + c * S1_CH + row * S1_ROW + q * 4, src, true);
    }
    // ---- second interior: 8ch x 30 rows x 8 float4 = 1920 units (5 iters) ----
#pragma unroll
    for (int it = 0; it < 5; ++it) {
        int u = tid + it * NT;
        int c = u / 240;
        int rem = u - c * 240;
        int row = rem >> 3;
        int q = rem & 7;
        int gy = y0 - 3 + row;
        bool p = (gy >= 0) && (gy < H_);
        int gyc = gy < 0 ? 0 : (gy >= H_ ? H_ - 1 : gy);
        const float* src = sbase + (size_t)(c0 + c) * HW + (size_t)gyc * W_ + x0 + q * 4;
        cp16(s2 + c * S2_CH + row * S2_ROW + 4 + q * 4, src, p);
    }
    // ---- second edges: 8ch x 30 rows x 6 scalars = 1440 units (4 iters) ----
#pragma unroll
    for (int it = 0; it < 4; ++it) {
        int u = tid + it * NT;
        if (it < 3 || u < 1440) {
            int c = u / 180;
            int rem = u - c * 180;
            int row = rem / 6;
            int e = rem - row * 6;
            int x = (e < 3) ? (e - 3) : (TX + e - 3);   // -3,-2,-1,32,33,34
            int gy = y0 - 3 + row;
            int gx = x0 + x;
            bool p = (gy >= 0) && (gy < H_) && (gx >= 0) && (gx < W_);
            int gyc = gy < 0 ? 0 : (gy >= H_ ? H_ - 1 : gy);
            int gxc = gx < 0 ? 0 : (gx >= W_ ? W_ - 1 : gx);
            const float* src = sbase + (size_t)(c0 + c) * HW + (size_t)gyc * W_ + gxc;
            cp4(s2 + c * S2_CH + row * S2_ROW + (x + 4), src, p);
        }
    }
}

// One smem row, displacements di in [DI0, DI1), 8 px per thread.
// vaddr = byte addr of row at float index txl*8. j = di + p + 1.
// acc packed as (di-DI0)*8 + p.
template<int DI0, int DI1>
__device__ __forceinline__ void row_acc(
    uint32_t vaddr, const float (&f)[8], float* __restrict__ acc)
{
    constexpr int B0 = (DI0 + 1) / 4;
    constexpr int B1 = (DI1 + 7) / 4;   // max j = (DI1-1)+7+1
    float v[16];
#pragma unroll
    for (int bq = B0; bq <= B1; ++bq) {
        float4 t = lds128(vaddr + bq * 16);
        v[bq * 4 + 0] = t.x; v[bq * 4 + 1] = t.y;
        v[bq * 4 + 2] = t.z; v[bq * 4 + 3] = t.w;
    }
#pragma unroll
    for (int di = DI0; di < DI1; ++di) {
#pragma unroll
        for (int p = 0; p < 8; ++p)
            acc[(di - DI0) * 8 + p] += f[p] * v[di + p + 1];
    }
}

// Groups (contiguous flattened d = rr*7 + di):
// G0: d[ 0,12) = rr0[0,7) rr1[0,5)        -> 96 acc
// G1: d[12,24) = rr1[5,7) rr2[0,7) rr3[0,3) -> 96 acc
// G2: d[24,36) = rr3[3,7) rr4[0,7) rr5[0,1) -> 96 acc
// G3: d[36,49) = rr5[1,7) rr6[0,7)        -> 104 acc
template<int G>
__device__ __forceinline__ void accumulate(
    uint32_t s1a, uint32_t s2a, float* __restrict__ acc)
{
#pragma unroll 1
    for (int c = 0; c < KC; ++c) {
        float4 fa = lds128(s1a);
        float4 fb = lds128(s1a + 16);
        float f[8] = { fa.x, fa.y, fa.z, fa.w, fb.x, fb.y, fb.z, fb.w };
        s1a += S1_CH * 4;

        if (G == 0) {
            row_acc<0, 7>(s2a + 0 * (S2_ROW * 4), f, acc + 0);
            row_acc<0, 5>(s2a + 1 * (S2_ROW * 4), f, acc + 56);
        } else if (G == 1) {
            row_acc<5, 7>(s2a + 1 * (S2_ROW * 4), f, acc + 0);
            row_acc<0, 7>(s2a + 2 * (S2_ROW * 4), f, acc + 16);
            row_acc<0, 3>(s2a + 3 * (S2_ROW * 4), f, acc + 72);
        } else if (G == 2) {
            row_acc<3, 7>(s2a + 3 * (S2_ROW * 4), f, acc + 0);
            row_acc<0, 7>(s2a + 4 * (S2_ROW * 4), f, acc + 32);
            row_acc<0, 1>(s2a + 5 * (S2_ROW * 4), f, acc + 88);
        } else {
            row_acc<1, 7>(s2a + 5 * (S2_ROW * 4), f, acc + 0);
            row_acc<0, 7>(s2a + 6 * (S2_ROW * 4), f, acc + 48);
        }
        s2a += S2_CH * 4;
    }
}

template<int NSEG>
__device__ __forceinline__ void store_seg(
    float* __restrict__ op, const float* __restrict__ acc)
{
    const float invC = 1.0f / (float)C_;
#pragma unroll
    for (int i = 0; i < NSEG; ++i) {
        float4 o0, o1;
        o0.x = acc[i * 8 + 0] * invC;
        o0.y = acc[i * 8 + 1] * invC;
        o0.z = acc[i * 8 + 2] * invC;
        o0.w = acc[i * 8 + 3] * invC;
        o1.x = acc[i * 8 + 4] * invC;
        o1.y = acc[i * 8 + 5] * invC;
        o1.z = acc[i * 8 + 6] * invC;
        o1.w = acc[i * 8 + 7] * invC;
        ((float4*)op)[0] = o0;
        ((float4*)op)[1] = o1;
        op += (size_t)H_ * W_;
    }
}

__global__ void __launch_bounds__(NT, 1)
corr_kernel(const float* __restrict__ first,
            const float* __restrict__ second,
            float* __restrict__ out)
{
    extern __shared__ float smem[];
    const int tid = threadIdx.x;
    const int wg   = tid / 96;        // group 0..3 (displacement split)
    const int wtid = tid - wg * 96;
    const int bx = blockIdx.x, by = blockIdx.y, b = blockIdx.z;
    const int x0 = bx * TX, y0 = by * TY;
    const int txl = wtid & 3;         // 0..3, owns 8 x-pixels
    const int tyl = wtid >> 2;        // 0..23, one y-row

    const size_t HW = (size_t)H_ * W_;
    const float* fbase = first  + (size_t)b * C_ * HW;
    const float* sbase = second + (size_t)b * C_ * HW;

    const uint32_t smem_base = sptr(smem);
    const uint32_t s1_thr = smem_base + (uint32_t)(tyl * S1_ROW + txl * 8) * 4;
    const uint32_t s2_thr = smem_base + (uint32_t)S1_SIZE * 4
                          + (uint32_t)(tyl * S2_ROW + txl * 8) * 4;

    float acc[104];
#pragma unroll
    for (int i = 0; i < 104; ++i) acc[i] = 0.0f;

    load_chunk(smem, smem + S1_SIZE, fbase, sbase, 0, x0, y0, tid);
    cp_commit();

#pragma unroll 1
    for (int k = 0; k < NCHUNK; ++k) {
        if (k < NCHUNK - 1) {
            float* nb = smem + ((k + 1) & 1) * BUF_SIZE;
            load_chunk(nb, nb + S1_SIZE, fbase, sbase, (k + 1) * KC, x0, y0, tid);
            cp_commit();
            asm volatile("cp.async.wait_group 1;\n" ::: "memory");
        } else {
            asm volatile("cp.async.wait_group 0;\n" ::: "memory");
        }
        __syncthreads();

        const uint32_t boff = (uint32_t)((k & 1) * BUF_SIZE * 4);
        if (wg == 0)      accumulate<0>(s1_thr + boff, s2_thr + boff, acc);
        else if (wg == 1) accumulate<1>(s1_thr + boff, s2_thr + boff, acc);
        else if (wg == 2) accumulate<2>(s1_thr + boff, s2_thr + boff, acc);
        else              accumulate<3>(s1_thr + boff, s2_thr + boff, acc);

        __syncthreads();
    }

    const int y = y0 + tyl;
    const int x = x0 + txl * 8;
    float* op = out + (((size_t)b * ND + wg * 12) * H_ + y) * W_ + x;
    if (wg < 3) store_seg<12>(op, acc);
    else        store_seg<13>(op, acc);
}

extern "C" void kernel_launch(void* const* d_in, const int* in_sizes, int n_in,
                              void* d_out, int out_size)
{
    const float* first  = (const float*)d_in[0];
    const float* second = (const float*)d_in[1];
    float* out = (float*)d_out;

    cudaFuncSetAttribute(corr_kernel,
                         cudaFuncAttributeMaxDynamicSharedMemorySize,
                         (int)SMEM_BYTES);

    dim3 grid(W_ / TX, H_ / TY, B_);   // 14 x 8 x 8 = 896 CTAs
    dim3 block(NT);
    corr_kernel<<<grid, block, SMEM_BYTES>>>(first, second, out);
}